// round 11
// baseline (speedup 1.0000x reference)
#include <cuda_runtime.h>
#include <cuda_bf16.h>
#include <math.h>
#include <stdint.h>

#define CHANNEL   256
#define MEM_SIZE  684
#define POS_NUM   128
#define NEG_NUM   512
#define CLASS_NUM 60
#define BANK_ROWS 41040          // MEM_SIZE * CLASS_NUM
#define BANK_PAD  41088          // 321 * 128
#define BATCH     512
#define SEL_T     256
#define SCAP      2048           // smem candidate capacity
#define CAPG      4096           // global candidate capacity per row
#define NW_MASK   ((BANK_ROWS + 31) / 32)
#define TH_HARD   0.115f
#define TH_RAND   0.02f

// ---------------- scratch (static device globals) ------------------------------
__device__ __nv_bfloat16 g_bank_bf[(size_t)BANK_PAD * CHANNEL];   // 21 MB
__device__ __nv_bfloat16 g_f_bf[(size_t)BATCH * CHANNEL];
__device__ float  g_flag[BANK_ROWS];
__device__ float  g_ap[(size_t)BATCH * BANK_ROWS];                // 84 MB
__device__ unsigned g_masks[CLASS_NUM][NW_MASK];                  // 308 KB
__device__ double g_partial[BATCH];
// candidate buffers filled by gemm epilogue / rand filter
__device__ unsigned g_candHk[BATCH][CAPG];
__device__ int      g_candHi[BATCH][CAPG];
__device__ unsigned g_candRk[BATCH][CAPG];
__device__ int      g_candRi[BATCH][CAPG];
__device__ int      g_cntH[BATCH];
__device__ int      g_cntR[BATCH];

// ---------------- helpers ------------------------------------------------------
__device__ __forceinline__ uint32_t smem_u32(const void* p) {
    uint32_t a;
    asm("{ .reg .u64 t; cvta.to.shared.u64 t, %1; cvt.u32.u64 %0, t; }" : "=r"(a) : "l"(p));
    return a;
}
__device__ __forceinline__ unsigned key_asc(float x) {
    unsigned u = __float_as_uint(x);
    return (u & 0x80000000u) ? ~u : (u | 0x80000000u);
}
__device__ __forceinline__ float key_dec(unsigned k) {
    unsigned u = (k & 0x80000000u) ? (k ^ 0x80000000u) : ~k;
    return __uint_as_float(u);
}
__device__ __forceinline__ void aggInc(int* hist, unsigned b) {
    unsigned am = __activemask();
    unsigned same = __match_any_sync(am, b);
    int lead = __ffs(same) - 1;
    if ((int)(threadIdx.x & 31) == lead) atomicAdd(&hist[b], __popc(same));
}

// ---------------- prep kernels --------------------------------------------------
__global__ void convert_kernel(const float* __restrict__ bank,
                               const float* __restrict__ flag,
                               const float* __restrict__ f) {
    size_t tid = (size_t)blockIdx.x * blockDim.x + threadIdx.x;
    size_t stride = (size_t)gridDim.x * blockDim.x;
    if (tid < BATCH) { g_cntH[tid] = 0; g_cntR[tid] = 0; }   // reset per launch
    size_t total4 = (size_t)BANK_PAD * CHANNEL / 4;
    size_t real4  = (size_t)BANK_ROWS * CHANNEL / 4;
    for (size_t i = tid; i < total4; i += stride) {
        float4 v = make_float4(0.f, 0.f, 0.f, 0.f);
        if (i < real4) v = ((const float4*)bank)[i];
        __nv_bfloat162 lo(__float2bfloat16(v.x), __float2bfloat16(v.y));
        __nv_bfloat162 hi(__float2bfloat16(v.z), __float2bfloat16(v.w));
        ((__nv_bfloat162*)g_bank_bf)[2 * i]     = lo;
        ((__nv_bfloat162*)g_bank_bf)[2 * i + 1] = hi;
    }
    for (size_t i = tid; i < BANK_ROWS; i += stride) g_flag[i] = flag[i];
    size_t f4 = (size_t)BATCH * CHANNEL / 4;
    for (size_t i = tid; i < f4; i += stride) {
        float4 v = ((const float4*)f)[i];
        __nv_bfloat162 lo(__float2bfloat16(v.x), __float2bfloat16(v.y));
        __nv_bfloat162 hi(__float2bfloat16(v.z), __float2bfloat16(v.w));
        ((__nv_bfloat162*)g_f_bf)[2 * i]     = lo;
        ((__nv_bfloat162*)g_f_bf)[2 * i + 1] = hi;
    }
}

__global__ void scatter_kernel(const float* __restrict__ f, const int* __restrict__ idx) {
    int n = blockIdx.x;
    int r = idx[n];
    float4 v = ((const float4*)(f + (size_t)n * CHANNEL))[threadIdx.x];
    __nv_bfloat162 lo(__float2bfloat16(v.x), __float2bfloat16(v.y));
    __nv_bfloat162 hi(__float2bfloat16(v.z), __float2bfloat16(v.w));
    __nv_bfloat162* dst = (__nv_bfloat162*)(g_bank_bf + (size_t)r * CHANNEL) + 2 * threadIdx.x;
    dst[0] = lo; dst[1] = hi;
    if (threadIdx.x == 0) g_flag[r] = 1.0f;
}

__global__ void mask_kernel() {
    int lab = blockIdx.x;
    for (int w = threadIdx.x; w < NW_MASK; w += blockDim.x) {
        unsigned m = 0;
        int base = w * 32;
        int lim = BANK_ROWS - base; if (lim > 32) lim = 32;
        for (int e = 0; e < lim; e++) {
            int i = base + e;
            if ((i % CLASS_NUM) != lab && g_flag[i] > 0.f) m |= (1u << e);
        }
        g_masks[lab][w] = m;
    }
}

// ---------------- rand filter: stream rnd, append small-key candidates ---------
#define RF_CHUNK 1288            // float4 per block chunk (8 chunks cover 10260)
__global__ void __launch_bounds__(256, 4) randfilter_kernel(const float* __restrict__ rand_neg) {
    int n = blockIdx.y;
    const float4* rnd4 = (const float4*)(rand_neg + (size_t)n * BANK_ROWS);
    const int NV4 = BANK_ROWS / 4;
    int j0 = blockIdx.x * RF_CHUNK;
    int j1 = j0 + RF_CHUNK; if (j1 > NV4) j1 = NV4;
    for (int j = j0 + threadIdx.x; j < j1; j += 256 * 2) {
        int j2 = j + 256;
        float4 r0 = rnd4[j];
        float4 r1 = (j2 < j1) ? rnd4[j2] : make_float4(1.f, 1.f, 1.f, 1.f);
        float rv[8] = {r0.x, r0.y, r0.z, r0.w, r1.x, r1.y, r1.z, r1.w};
#pragma unroll
        for (int e = 0; e < 8; e++) {
            if (rv[e] < TH_RAND) {
                int idx = ((e < 4) ? j : j2) * 4 + (e & 3);
                int p = atomicAdd(&g_cntR[n], 1);
                if (p < CAPG) { g_candRk[n][p] = key_asc(rv[e]); g_candRi[n][p] = idx; }
            }
        }
    }
}

// ---------------- mma.sync bf16 GEMM + fused hard-candidate filter -------------
#define SMEM_STRIDE 72
__global__ void __launch_bounds__(256, 2) gemm_mma_kernel() {
    __shared__ __nv_bfloat16 As[128][SMEM_STRIDE];
    __shared__ __nv_bfloat16 Bs[128][SMEM_STRIDE];
    int tid = threadIdx.x, lane = tid & 31, wid = tid >> 5;
    int wm = wid >> 2, wn = wid & 3;
    int bm = blockIdx.y * 128, bn = blockIdx.x * 128;
    const __nv_bfloat16* Ag = g_f_bf    + (size_t)bm * CHANNEL;
    const __nv_bfloat16* Bg = g_bank_bf + (size_t)bn * CHANNEL;
    float acc[4][4][4];
#pragma unroll
    for (int i = 0; i < 4; i++)
#pragma unroll
        for (int j = 0; j < 4; j++)
#pragma unroll
            for (int k = 0; k < 4; k++) acc[i][j][k] = 0.f;
    int lrow = tid >> 3, lcol = (tid & 7) * 8;
#pragma unroll
    for (int kc = 0; kc < 4; kc++) {
        int k0 = kc * 64;
#pragma unroll
        for (int it = 0; it < 4; it++) {
            int row = lrow + it * 32;
            *(uint4*)&As[row][lcol] = *(const uint4*)(Ag + (size_t)row * CHANNEL + k0 + lcol);
            *(uint4*)&Bs[row][lcol] = *(const uint4*)(Bg + (size_t)row * CHANNEL + k0 + lcol);
        }
        __syncthreads();
#pragma unroll
        for (int ks = 0; ks < 4; ks++) {
            int kk = ks * 16;
            uint32_t af[4][4], bfr[4][2];
#pragma unroll
            for (int mt = 0; mt < 4; mt++) {
                int row = wm * 64 + mt * 16 + (lane & 15);
                int col = kk + (lane >> 4) * 8;
                uint32_t a = smem_u32(&As[row][col]);
                asm volatile("ldmatrix.sync.aligned.m8n8.x4.shared.b16 {%0,%1,%2,%3}, [%4];"
                    : "=r"(af[mt][0]), "=r"(af[mt][1]), "=r"(af[mt][2]), "=r"(af[mt][3]) : "r"(a));
            }
#pragma unroll
            for (int g = 0; g < 2; g++) {
                int ntile = g * 2 + (lane >> 4);
                int khalf = (lane >> 3) & 1;
                int row = wn * 32 + ntile * 8 + (lane & 7);
                int col = kk + khalf * 8;
                uint32_t a = smem_u32(&Bs[row][col]);
                uint32_t b0, b1, b2, b3;
                asm volatile("ldmatrix.sync.aligned.m8n8.x4.shared.b16 {%0,%1,%2,%3}, [%4];"
                    : "=r"(b0), "=r"(b1), "=r"(b2), "=r"(b3) : "r"(a));
                bfr[g * 2][0] = b0; bfr[g * 2][1] = b1;
                bfr[g * 2 + 1][0] = b2; bfr[g * 2 + 1][1] = b3;
            }
#pragma unroll
            for (int mt = 0; mt < 4; mt++)
#pragma unroll
                for (int nt = 0; nt < 4; nt++) {
                    asm volatile(
                        "mma.sync.aligned.m16n8k16.row.col.f32.bf16.bf16.f32 "
                        "{%0,%1,%2,%3}, {%4,%5,%6,%7}, {%8,%9}, {%0,%1,%2,%3};"
                        : "+f"(acc[mt][nt][0]), "+f"(acc[mt][nt][1]),
                          "+f"(acc[mt][nt][2]), "+f"(acc[mt][nt][3])
                        : "r"(af[mt][0]), "r"(af[mt][1]), "r"(af[mt][2]), "r"(af[mt][3]),
                          "r"(bfr[nt][0]), "r"(bfr[nt][1]));
                }
        }
        __syncthreads();
    }
    int r0 = lane >> 2, c0 = (lane & 3) * 2;
#pragma unroll
    for (int mt = 0; mt < 4; mt++) {
        int row = bm + wm * 64 + mt * 16 + r0;
#pragma unroll
        for (int nt = 0; nt < 4; nt++) {
            int col = bn + wn * 32 + nt * 8 + c0;
            if (col < BANK_ROWS) {
                float* d = g_ap + (size_t)row * BANK_ROWS + col;
                *(float2*)d = make_float2(acc[mt][nt][0], acc[mt][nt][1]);
                *(float2*)(d + (size_t)8 * BANK_ROWS) = make_float2(acc[mt][nt][2], acc[mt][nt][3]);
                // fused hard-candidate filter (values still in registers)
#pragma unroll
                for (int q = 0; q < 4; q++) {
                    float v = acc[mt][nt][q];
                    if (v > TH_HARD) {
                        int rr = row + (q >> 1) * 8;
                        int cc = col + (q & 1);
                        int p = atomicAdd(&g_cntH[rr], 1);
                        if (p < CAPG) { g_candHk[rr][p] = ~key_asc(v); g_candHi[rr][p] = cc; }
                    }
                }
            }
        }
    }
}

// ---------------- selection helpers --------------------------------------------
__device__ __forceinline__ void pick_bucket(const int* hist, int nb, int kk,
                                            int* s_coarse, int* s_b, int* s_kk) {
    int tid = threadIdx.x;
    int chunk = (nb >> 8) ? (nb >> 8) : 1;
    int nc = nb / chunk;
    if (tid < nc) {
        int part = 0;
        for (int j = 0; j < chunk; j++) part += hist[tid * chunk + j];
        s_coarse[tid] = part;
    }
    __syncthreads();
    if (tid == 0) {
        int cum = 0, cb = 0;
        for (; cb < nc - 1; cb++) {
            if (cum + s_coarse[cb] >= kk) break;
            cum += s_coarse[cb];
        }
        int b = cb * chunk;
        for (;; b++) { if (cum + hist[b] >= kk) break; cum += hist[b]; }
        *s_b = b; *s_kk = kk - cum;
    }
    __syncthreads();
}

__device__ unsigned cand_radix(const unsigned* cand, int cnt, int kk0, int shift0,
                               unsigned pref0, int* hist, int* s_coarse,
                               int* s_b, int* s_kk, int* need_out) {
    int tid = threadIdx.x;
    unsigned pref = pref0;
    int shift = shift0, kk = kk0;
    while (shift > 0) {
        int bits = (shift >= 11) ? 11 : shift;
        int nsh = shift - bits;
        int nb = 1 << bits;
        __syncthreads();
        for (int i = tid; i < nb; i += SEL_T) hist[i] = 0;
        __syncthreads();
        for (int j = tid; j < cnt; j += SEL_T) {
            unsigned k = cand[j];
            unsigned hi = (shift >= 32) ? 0u : (k >> shift);
            if (hi == pref) atomicAdd(&hist[(k >> nsh) & (nb - 1)], 1);
        }
        __syncthreads();
        pick_bucket(hist, nb, kk, s_coarse, s_b, s_kk);
        pref = (pref << bits) | (unsigned)(*s_b);
        kk = *s_kk;
        shift = nsh;
        __syncthreads();
    }
    *need_out = kk;
    return pref;
}

__device__ unsigned glob_radix(int mode, const float* __restrict__ ap,
                               const float* __restrict__ rnd,
                               const unsigned* __restrict__ s_mask,
                               int K, int* hist, int* s_coarse,
                               int* s_b, int* s_kk, int* p_need) {
    int tid = threadIdx.x;
    unsigned prefix = 0;
    int kk = K, shift = 32;
    for (int pass = 0; pass < 3; pass++) {
        int bits = (pass < 2) ? 11 : 10;
        shift -= bits;
        int nb = 1 << bits;
        __syncthreads();
        for (int i = tid; i < nb; i += SEL_T) hist[i] = 0;
        __syncthreads();
        for (int i = tid; i < BANK_ROWS; i += SEL_T) {
            bool valid = (s_mask[i >> 5] >> (i & 31)) & 1u;
            unsigned key = 0xFFFFFFFFu;
            if (valid) key = (mode == 0) ? ~key_asc(ap[i]) : key_asc(rnd[i]);
            if (pass == 0 || (key >> (shift + bits)) == prefix)
                aggInc(hist, (key >> shift) & (nb - 1));
        }
        __syncthreads();
        pick_bucket(hist, nb, kk, s_coarse, s_b, s_kk);
        prefix = (prefix << bits) | (unsigned)(*s_b);
        kk = *s_kk;
        __syncthreads();
    }
    *p_need = kk;
    return prefix;
}

__device__ double block_red(double v, double* s_warp) {
#pragma unroll
    for (int o = 16; o; o >>= 1) v += __shfl_down_sync(0xffffffffu, v, o);
    int w = threadIdx.x >> 5;
    if ((threadIdx.x & 31) == 0) s_warp[w] = v;
    __syncthreads();
    double r = 0;
    if (threadIdx.x == 0) for (int i = 0; i < (SEL_T / 32); i++) r += s_warp[i];
    __syncthreads();
    return r;
}

#define MBIT(i) ((s_mask[(i) >> 5] >> ((i) & 31)) & 1u)

// ---------------- per-row selection + loss (candidate-driven, no full scans) ---
__global__ void __launch_bounds__(SEL_T, 4) select_kernel(const int* __restrict__ label,
                                                          const float* __restrict__ rand_neg) {
    __shared__ unsigned s_mask[NW_MASK];
    __shared__ unsigned s_ck[SCAP];
    __shared__ unsigned s_rk[SCAP];
    __shared__ int      s_ri[SCAP];
    __shared__ int      hist[2048];
    __shared__ unsigned s_posk[MEM_SIZE];
    __shared__ int      s_coarse[256];
    __shared__ float    s_posv[POS_NUM];
    __shared__ int      s_tie[256];
    __shared__ double   s_warp[SEL_T / 32];
    __shared__ int      s_b, s_kk, s_cnt;
    __shared__ double   s_Sh, s_Sr;

    int n = blockIdx.x;
    int tid = threadIdx.x;
    int lab = label[n];
    const float* ap  = g_ap + (size_t)n * BANK_ROWS;
    const float* rnd = rand_neg + (size_t)n * BANK_ROWS;

    for (int w = tid; w < NW_MASK; w += SEL_T) s_mask[w] = g_masks[lab][w];
    __syncthreads();

    // ===== hard negatives =====
    int rawH = g_cntH[n];
    if (tid == 0) s_cnt = 0;
    __syncthreads();
    {
        int lim = rawH < CAPG ? rawH : CAPG;
        for (int j = tid; j < lim; j += SEL_T) {
            int idx = g_candHi[n][j];
            if (MBIT(idx)) {
                int p = atomicAdd(&s_cnt, 1);
                if (p < SCAP) s_ck[p] = g_candHk[n][j];
            }
        }
    }
    __syncthreads();
    int vH = s_cnt;
    if (rawH <= CAPG && vH >= NEG_NUM && vH <= SCAP) {
        int needH;
        unsigned Th = cand_radix(s_ck, vH, NEG_NUM, 32, 0u, hist, s_coarse, &s_b, &s_kk, &needH);
        double sumH = 0.0;
        for (int j = tid; j < vH; j += SEL_T) {
            unsigned k = s_ck[j];
            if (k < Th) sumH += (double)__expf(key_dec(~k));
        }
        double Sh = block_red(sumH, s_warp);
        if (tid == 0) s_Sh = Sh + (double)needH * (double)__expf(key_dec(~Th));
    } else {
        int needH;
        unsigned Th = glob_radix(0, ap, rnd, s_mask, NEG_NUM, hist, s_coarse, &s_b, &s_kk, &needH);
        double sumH = 0.0;
        for (int i = tid; i < BANK_ROWS; i += SEL_T) {
            if (MBIT(i)) {
                float v = ap[i];
                if (~key_asc(v) < Th) sumH += (double)__expf(v);
            }
        }
        double Sh = block_red(sumH, s_warp);
        if (tid == 0) s_Sh = Sh + (double)needH * (double)__expf(key_dec(~Th));
    }
    __syncthreads();

    // ===== random negatives =====
    int rawR = g_cntR[n];
    if (tid == 0) s_cnt = 0;
    __syncthreads();
    {
        int lim = rawR < CAPG ? rawR : CAPG;
        for (int j = tid; j < lim; j += SEL_T) {
            int idx = g_candRi[n][j];
            if (MBIT(idx)) {
                int p = atomicAdd(&s_cnt, 1);
                if (p < SCAP) { s_rk[p] = g_candRk[n][j]; s_ri[p] = idx; }
            }
        }
    }
    __syncthreads();
    int vR = s_cnt;
    if (rawR <= CAPG && vR >= NEG_NUM && vR <= SCAP) {
        int needR;
        unsigned Tr = cand_radix(s_rk, vR, NEG_NUM, 32, 0u, hist, s_coarse, &s_b, &s_kk, &needR);
        if (tid == 0) s_cnt = 0;
        __syncthreads();
        double sumR = 0.0;
        for (int j = tid; j < vR; j += SEL_T) {
            unsigned k = s_rk[j];
            if (k < Tr) sumR += (double)__expf(ap[s_ri[j]]);
            else if (k == Tr) {
                int p = atomicAdd(&s_cnt, 1);
                if (p < 256) s_tie[p] = s_ri[j];
            }
        }
        __syncthreads();
        double Sr = block_red(sumR, s_warp);
        if (tid == 0) {
            int c = s_cnt < 256 ? s_cnt : 256;
            int take = needR < c ? needR : c;
            double add = 0.0;
            for (int t = 0; t < take; t++) {          // smallest column indices first
                int best = 0x7fffffff, bi = -1;
                for (int j = 0; j < c; j++)
                    if (s_tie[j] >= 0 && s_tie[j] < best) { best = s_tie[j]; bi = j; }
                s_tie[bi] = -1;
                add += (double)__expf(ap[best]);
            }
            s_Sr = Sr + add;
        }
    } else {
        int needR;
        unsigned Tr = glob_radix(1, ap, rnd, s_mask, NEG_NUM, hist, s_coarse, &s_b, &s_kk, &needR);
        if (tid == 0) s_cnt = 0;
        __syncthreads();
        double sumR = 0.0;
        for (int i = tid; i < BANK_ROWS; i += SEL_T) {
            if (MBIT(i)) {
                unsigned kr = key_asc(rnd[i]);
                if (kr < Tr) sumR += (double)__expf(ap[i]);
                else if (kr == Tr) {
                    int p = atomicAdd(&s_cnt, 1);
                    if (p < 256) s_tie[p] = i;
                }
            }
        }
        __syncthreads();
        double Sr = block_red(sumR, s_warp);
        if (tid == 0) {
            int c = s_cnt < 256 ? s_cnt : 256;
            int take = needR < c ? needR : c;
            double add = 0.0;
            for (int t = 0; t < take; t++) {
                int best = 0x7fffffff, bi = -1;
                for (int j = 0; j < c; j++)
                    if (s_tie[j] >= 0 && s_tie[j] < best) { best = s_tie[j]; bi = j; }
                s_tie[bi] = -1;
                add += (double)__expf(ap[best]);
            }
            s_Sr = Sr + add;
        }
    }
    __syncthreads();

    // ===== positives: 684 gathers + smem radix =====
    for (int i = tid; i < MEM_SIZE; i += SEL_T) {
        int m = lab + CLASS_NUM * i;
        s_posk[i] = (g_flag[m] > 0.f) ? key_asc(ap[m]) : 0xFFFFFFFFu;
    }
    __syncthreads();
    int needP;
    unsigned Tp = cand_radix(s_posk, MEM_SIZE, POS_NUM, 32, 0u, hist, s_coarse, &s_b, &s_kk, &needP);
    if (tid == 0) s_cnt = 0;
    __syncthreads();
    for (int i = tid; i < MEM_SIZE; i += SEL_T) {
        unsigned k = s_posk[i];
        if (k < Tp) {
            int p = atomicAdd(&s_cnt, 1);
            s_posv[p] = key_dec(k);
        }
    }
    __syncthreads();
    if (tid == 0) {
        float tv = key_dec(Tp);
        int base = s_cnt;                              // == POS_NUM - needP
        for (int t = 0; t < needP; t++) s_posv[base + t] = tv;
    }
    __syncthreads();

    // ===== loss partial =====
    double Shv = s_Sh, Srv = s_Sr;
    double l = 0.0;
    if (tid < POS_NUM) {
        double p = (double)s_posv[tid];
        double ep = exp(p);
        l = 2.0 * p - log(ep + Shv) - log(ep + Srv);
    }
    double tot = block_red(l, s_warp);
    if (tid == 0) g_partial[n] = tot;
}

// ---------------- finalize ------------------------------------------------------
__global__ void finalize_kernel(float* __restrict__ out) {
    __shared__ double s_warp[16];
    int tid = threadIdx.x;
    double v = g_partial[tid];
#pragma unroll
    for (int o = 16; o; o >>= 1) v += __shfl_down_sync(0xffffffffu, v, o);
    if ((tid & 31) == 0) s_warp[tid >> 5] = v;
    __syncthreads();
    if (tid == 0) {
        double t = 0;
        for (int i = 0; i < 16; i++) t += s_warp[i];
        out[0] = (float)(-t / (double)(BATCH * 2 * POS_NUM));
    }
}

// ---------------- launch --------------------------------------------------------
extern "C" void kernel_launch(void* const* d_in, const int* in_sizes, int n_in,
                              void* d_out, int out_size) {
    const float* f        = (const float*)d_in[0];
    const int*   label    = (const int*)d_in[1];
    const int*   enq      = (const int*)d_in[2];
    const float* bank     = (const float*)d_in[3];
    const float* flag     = (const float*)d_in[4];
    const float* rand_neg = (const float*)d_in[5];
    float* out = (float*)d_out;

    convert_kernel<<<1024, 256>>>(bank, flag, f);   // also zeroes candidate counters
    scatter_kernel<<<BATCH, 64>>>(f, enq);
    mask_kernel<<<CLASS_NUM, 256>>>();
    randfilter_kernel<<<dim3(8, BATCH), 256>>>(rand_neg);
    dim3 g(BANK_PAD / 128, BATCH / 128);
    gemm_mma_kernel<<<g, 256>>>();
    select_kernel<<<BATCH, SEL_T>>>(label, rand_neg);
    finalize_kernel<<<1, 512>>>(out);
}

// round 16
// speedup vs baseline: 1.3190x; 1.3190x over previous
#include <cuda_runtime.h>
#include <cuda_bf16.h>
#include <math.h>
#include <stdint.h>

#define CHANNEL   256
#define MEM_SIZE  684
#define POS_NUM   128
#define NEG_NUM   512
#define CLASS_NUM 60
#define BANK_ROWS 41040          // MEM_SIZE * CLASS_NUM
#define BANK_PAD  41088          // 321 * 128
#define BATCH     512
#define SEL_T     256
#define SCAP      2048           // smem candidate capacity
#define CAPG      4096           // global candidate capacity per row
#define NW_MASK   ((BANK_ROWS + 31) / 32)
#define TH_HARD   0.115f
#define TH_RAND   0.02f

// ---------------- scratch (static device globals) ------------------------------
__device__ __nv_bfloat16 g_bank_bf[(size_t)BANK_PAD * CHANNEL];   // 21 MB
__device__ __nv_bfloat16 g_f_bf[(size_t)BATCH * CHANNEL];
__device__ float  g_flag[BANK_ROWS];
__device__ float  g_ap[(size_t)BATCH * BANK_ROWS];                // 84 MB
__device__ unsigned g_masks[CLASS_NUM][NW_MASK];                  // 308 KB
__device__ double g_partial[BATCH];
__device__ unsigned g_candHk[BATCH][CAPG];
__device__ int      g_candHi[BATCH][CAPG];
__device__ unsigned g_candRk[BATCH][CAPG];
__device__ int      g_candRi[BATCH][CAPG];
__device__ int      g_cntH[BATCH];
__device__ int      g_cntR[BATCH];

// ---------------- helpers ------------------------------------------------------
__device__ __forceinline__ uint32_t smem_u32(const void* p) {
    uint32_t a;
    asm("{ .reg .u64 t; cvta.to.shared.u64 t, %1; cvt.u32.u64 %0, t; }" : "=r"(a) : "l"(p));
    return a;
}
__device__ __forceinline__ unsigned key_asc(float x) {
    unsigned u = __float_as_uint(x);
    return (u & 0x80000000u) ? ~u : (u | 0x80000000u);
}
__device__ __forceinline__ float key_dec(unsigned k) {
    unsigned u = (k & 0x80000000u) ? (k ^ 0x80000000u) : ~k;
    return __uint_as_float(u);
}
__device__ __forceinline__ void aggInc(int* hist, unsigned b) {
    unsigned am = __activemask();
    unsigned same = __match_any_sync(am, b);
    int lead = __ffs(same) - 1;
    if ((int)(threadIdx.x & 31) == lead) atomicAdd(&hist[b], __popc(same));
}

// ---------------- prep kernels --------------------------------------------------
__global__ void convert_kernel(const float* __restrict__ bank,
                               const float* __restrict__ flag,
                               const float* __restrict__ f) {
    size_t tid = (size_t)blockIdx.x * blockDim.x + threadIdx.x;
    size_t stride = (size_t)gridDim.x * blockDim.x;
    if (tid < BATCH) { g_cntH[tid] = 0; g_cntR[tid] = 0; }   // reset per launch
    size_t total4 = (size_t)BANK_PAD * CHANNEL / 4;
    size_t real4  = (size_t)BANK_ROWS * CHANNEL / 4;
    // 2x unrolled grid-stride (MLP 2)
    for (size_t i = tid; i < total4; i += 2 * stride) {
        size_t i2 = i + stride;
        float4 v1 = make_float4(0.f, 0.f, 0.f, 0.f);
        float4 v2 = make_float4(0.f, 0.f, 0.f, 0.f);
        if (i < real4) v1 = ((const float4*)bank)[i];
        if (i2 < total4 && i2 < real4) v2 = ((const float4*)bank)[i2];
        __nv_bfloat162 lo1(__float2bfloat16(v1.x), __float2bfloat16(v1.y));
        __nv_bfloat162 hi1(__float2bfloat16(v1.z), __float2bfloat16(v1.w));
        ((__nv_bfloat162*)g_bank_bf)[2 * i]     = lo1;
        ((__nv_bfloat162*)g_bank_bf)[2 * i + 1] = hi1;
        if (i2 < total4) {
            __nv_bfloat162 lo2(__float2bfloat16(v2.x), __float2bfloat16(v2.y));
            __nv_bfloat162 hi2(__float2bfloat16(v2.z), __float2bfloat16(v2.w));
            ((__nv_bfloat162*)g_bank_bf)[2 * i2]     = lo2;
            ((__nv_bfloat162*)g_bank_bf)[2 * i2 + 1] = hi2;
        }
    }
    for (size_t i = tid; i < BANK_ROWS; i += stride) g_flag[i] = flag[i];
    size_t f4 = (size_t)BATCH * CHANNEL / 4;
    for (size_t i = tid; i < f4; i += stride) {
        float4 v = ((const float4*)f)[i];
        __nv_bfloat162 lo(__float2bfloat16(v.x), __float2bfloat16(v.y));
        __nv_bfloat162 hi(__float2bfloat16(v.z), __float2bfloat16(v.w));
        ((__nv_bfloat162*)g_f_bf)[2 * i]     = lo;
        ((__nv_bfloat162*)g_f_bf)[2 * i + 1] = hi;
    }
}

__global__ void scatter_kernel(const float* __restrict__ f, const int* __restrict__ idx) {
    int n = blockIdx.x;
    int r = idx[n];
    float4 v = ((const float4*)(f + (size_t)n * CHANNEL))[threadIdx.x];
    __nv_bfloat162 lo(__float2bfloat16(v.x), __float2bfloat16(v.y));
    __nv_bfloat162 hi(__float2bfloat16(v.z), __float2bfloat16(v.w));
    __nv_bfloat162* dst = (__nv_bfloat162*)(g_bank_bf + (size_t)r * CHANNEL) + 2 * threadIdx.x;
    dst[0] = lo; dst[1] = hi;
    if (threadIdx.x == 0) g_flag[r] = 1.0f;
}

__global__ void mask_kernel() {
    int lab = blockIdx.x;
    for (int w = threadIdx.x; w < NW_MASK; w += blockDim.x) {
        unsigned m = 0;
        int base = w * 32;
        int lim = BANK_ROWS - base; if (lim > 32) lim = 32;
        for (int e = 0; e < lim; e++) {
            int i = base + e;
            if ((i % CLASS_NUM) != lab && g_flag[i] > 0.f) m |= (1u << e);
        }
        g_masks[lab][w] = m;
    }
}

// ---------------- mma.sync bf16 GEMM (clean R10 version) -----------------------
#define SMEM_STRIDE 72
__global__ void __launch_bounds__(256, 2) gemm_mma_kernel() {
    __shared__ __nv_bfloat16 As[128][SMEM_STRIDE];
    __shared__ __nv_bfloat16 Bs[128][SMEM_STRIDE];
    int tid = threadIdx.x, lane = tid & 31, wid = tid >> 5;
    int wm = wid >> 2, wn = wid & 3;
    int bm = blockIdx.y * 128, bn = blockIdx.x * 128;
    const __nv_bfloat16* Ag = g_f_bf    + (size_t)bm * CHANNEL;
    const __nv_bfloat16* Bg = g_bank_bf + (size_t)bn * CHANNEL;
    float acc[4][4][4];
#pragma unroll
    for (int i = 0; i < 4; i++)
#pragma unroll
        for (int j = 0; j < 4; j++)
#pragma unroll
            for (int k = 0; k < 4; k++) acc[i][j][k] = 0.f;
    int lrow = tid >> 3, lcol = (tid & 7) * 8;
#pragma unroll
    for (int kc = 0; kc < 4; kc++) {
        int k0 = kc * 64;
#pragma unroll
        for (int it = 0; it < 4; it++) {
            int row = lrow + it * 32;
            *(uint4*)&As[row][lcol] = *(const uint4*)(Ag + (size_t)row * CHANNEL + k0 + lcol);
            *(uint4*)&Bs[row][lcol] = *(const uint4*)(Bg + (size_t)row * CHANNEL + k0 + lcol);
        }
        __syncthreads();
#pragma unroll
        for (int ks = 0; ks < 4; ks++) {
            int kk = ks * 16;
            uint32_t af[4][4], bfr[4][2];
#pragma unroll
            for (int mt = 0; mt < 4; mt++) {
                int row = wm * 64 + mt * 16 + (lane & 15);
                int col = kk + (lane >> 4) * 8;
                uint32_t a = smem_u32(&As[row][col]);
                asm volatile("ldmatrix.sync.aligned.m8n8.x4.shared.b16 {%0,%1,%2,%3}, [%4];"
                    : "=r"(af[mt][0]), "=r"(af[mt][1]), "=r"(af[mt][2]), "=r"(af[mt][3]) : "r"(a));
            }
#pragma unroll
            for (int g = 0; g < 2; g++) {
                int ntile = g * 2 + (lane >> 4);
                int khalf = (lane >> 3) & 1;
                int row = wn * 32 + ntile * 8 + (lane & 7);
                int col = kk + khalf * 8;
                uint32_t a = smem_u32(&Bs[row][col]);
                uint32_t b0, b1, b2, b3;
                asm volatile("ldmatrix.sync.aligned.m8n8.x4.shared.b16 {%0,%1,%2,%3}, [%4];"
                    : "=r"(b0), "=r"(b1), "=r"(b2), "=r"(b3) : "r"(a));
                bfr[g * 2][0] = b0; bfr[g * 2][1] = b1;
                bfr[g * 2 + 1][0] = b2; bfr[g * 2 + 1][1] = b3;
            }
#pragma unroll
            for (int mt = 0; mt < 4; mt++)
#pragma unroll
                for (int nt = 0; nt < 4; nt++) {
                    asm volatile(
                        "mma.sync.aligned.m16n8k16.row.col.f32.bf16.bf16.f32 "
                        "{%0,%1,%2,%3}, {%4,%5,%6,%7}, {%8,%9}, {%0,%1,%2,%3};"
                        : "+f"(acc[mt][nt][0]), "+f"(acc[mt][nt][1]),
                          "+f"(acc[mt][nt][2]), "+f"(acc[mt][nt][3])
                        : "r"(af[mt][0]), "r"(af[mt][1]), "r"(af[mt][2]), "r"(af[mt][3]),
                          "r"(bfr[nt][0]), "r"(bfr[nt][1]));
                }
        }
        __syncthreads();
    }
    int r0 = lane >> 2, c0 = (lane & 3) * 2;
#pragma unroll
    for (int mt = 0; mt < 4; mt++) {
        int row = bm + wm * 64 + mt * 16 + r0;
#pragma unroll
        for (int nt = 0; nt < 4; nt++) {
            int col = bn + wn * 32 + nt * 8 + c0;
            if (col < BANK_ROWS) {
                float* d = g_ap + (size_t)row * BANK_ROWS + col;
                *(float2*)d = make_float2(acc[mt][nt][0], acc[mt][nt][1]);
                *(float2*)(d + (size_t)8 * BANK_ROWS) = make_float2(acc[mt][nt][2], acc[mt][nt][3]);
            }
        }
    }
}

// ---------------- filter: stream ap + rnd with MLP=8, push candidates ----------
#define F_CHUNK 2565             // NV4 / 4 exactly (10260 / 4)
__global__ void __launch_bounds__(256, 4) filter_kernel(const float* __restrict__ rand_neg) {
    int n = blockIdx.y;
    const float4* ap4  = (const float4*)(g_ap + (size_t)n * BANK_ROWS);
    const float4* rnd4 = (const float4*)(rand_neg + (size_t)n * BANK_ROWS);
    int j0 = blockIdx.x * F_CHUNK;
    int j1 = j0 + F_CHUNK;
    for (int j = j0 + threadIdx.x; j < j1; j += 256 * 4) {
        int jb = j + 256, jc = j + 512, jd = j + 768;
        // 8 independent loads issued before any consumption
        float4 a0 = ap4[j];
        float4 a1 = (jb < j1) ? ap4[jb] : make_float4(0.f, 0.f, 0.f, 0.f);
        float4 a2 = (jc < j1) ? ap4[jc] : make_float4(0.f, 0.f, 0.f, 0.f);
        float4 a3 = (jd < j1) ? ap4[jd] : make_float4(0.f, 0.f, 0.f, 0.f);
        float4 r0 = rnd4[j];
        float4 r1 = (jb < j1) ? rnd4[jb] : make_float4(1.f, 1.f, 1.f, 1.f);
        float4 r2 = (jc < j1) ? rnd4[jc] : make_float4(1.f, 1.f, 1.f, 1.f);
        float4 r3 = (jd < j1) ? rnd4[jd] : make_float4(1.f, 1.f, 1.f, 1.f);
        float4 aa[4] = {a0, a1, a2, a3};
        float4 rr[4] = {r0, r1, r2, r3};
#pragma unroll
        for (int u = 0; u < 4; u++) {
            int base = (j + u * 256) * 4;
            float av[4] = {aa[u].x, aa[u].y, aa[u].z, aa[u].w};
            float rv[4] = {rr[u].x, rr[u].y, rr[u].z, rr[u].w};
#pragma unroll
            for (int e = 0; e < 4; e++) {
                if (av[e] > TH_HARD) {
                    int p = atomicAdd(&g_cntH[n], 1);
                    if (p < CAPG) { g_candHk[n][p] = ~key_asc(av[e]); g_candHi[n][p] = base + e; }
                }
                if (rv[e] < TH_RAND) {
                    int p = atomicAdd(&g_cntR[n], 1);
                    if (p < CAPG) { g_candRk[n][p] = key_asc(rv[e]); g_candRi[n][p] = base + e; }
                }
            }
        }
    }
}

// ---------------- selection helpers --------------------------------------------
__device__ __forceinline__ void pick_bucket(const int* hist, int nb, int kk,
                                            int* s_coarse, int* s_b, int* s_kk) {
    int tid = threadIdx.x;
    int chunk = (nb >> 8) ? (nb >> 8) : 1;
    int nc = nb / chunk;
    if (tid < nc) {
        int part = 0;
        for (int j = 0; j < chunk; j++) part += hist[tid * chunk + j];
        s_coarse[tid] = part;
    }
    __syncthreads();
    if (tid == 0) {
        int cum = 0, cb = 0;
        for (; cb < nc - 1; cb++) {
            if (cum + s_coarse[cb] >= kk) break;
            cum += s_coarse[cb];
        }
        int b = cb * chunk;
        for (;; b++) { if (cum + hist[b] >= kk) break; cum += hist[b]; }
        *s_b = b; *s_kk = kk - cum;
    }
    __syncthreads();
}

__device__ unsigned cand_radix(const unsigned* cand, int cnt, int kk0, int shift0,
                               unsigned pref0, int* hist, int* s_coarse,
                               int* s_b, int* s_kk, int* need_out) {
    int tid = threadIdx.x;
    unsigned pref = pref0;
    int shift = shift0, kk = kk0;
    while (shift > 0) {
        int bits = (shift >= 11) ? 11 : shift;
        int nsh = shift - bits;
        int nb = 1 << bits;
        __syncthreads();
        for (int i = tid; i < nb; i += SEL_T) hist[i] = 0;
        __syncthreads();
        for (int j = tid; j < cnt; j += SEL_T) {
            unsigned k = cand[j];
            unsigned hi = (shift >= 32) ? 0u : (k >> shift);
            if (hi == pref) atomicAdd(&hist[(k >> nsh) & (nb - 1)], 1);
        }
        __syncthreads();
        pick_bucket(hist, nb, kk, s_coarse, s_b, s_kk);
        pref = (pref << bits) | (unsigned)(*s_b);
        kk = *s_kk;
        shift = nsh;
        __syncthreads();
    }
    *need_out = kk;
    return pref;
}

__device__ unsigned glob_radix(int mode, const float* __restrict__ ap,
                               const float* __restrict__ rnd,
                               const unsigned* __restrict__ s_mask,
                               int K, int* hist, int* s_coarse,
                               int* s_b, int* s_kk, int* p_need) {
    int tid = threadIdx.x;
    unsigned prefix = 0;
    int kk = K, shift = 32;
    for (int pass = 0; pass < 3; pass++) {
        int bits = (pass < 2) ? 11 : 10;
        shift -= bits;
        int nb = 1 << bits;
        __syncthreads();
        for (int i = tid; i < nb; i += SEL_T) hist[i] = 0;
        __syncthreads();
        for (int i = tid; i < BANK_ROWS; i += SEL_T) {
            bool valid = (s_mask[i >> 5] >> (i & 31)) & 1u;
            unsigned key = 0xFFFFFFFFu;
            if (valid) key = (mode == 0) ? ~key_asc(ap[i]) : key_asc(rnd[i]);
            if (pass == 0 || (key >> (shift + bits)) == prefix)
                aggInc(hist, (key >> shift) & (nb - 1));
        }
        __syncthreads();
        pick_bucket(hist, nb, kk, s_coarse, s_b, s_kk);
        prefix = (prefix << bits) | (unsigned)(*s_b);
        kk = *s_kk;
        __syncthreads();
    }
    *p_need = kk;
    return prefix;
}

__device__ double block_red(double v, double* s_warp) {
#pragma unroll
    for (int o = 16; o; o >>= 1) v += __shfl_down_sync(0xffffffffu, v, o);
    int w = threadIdx.x >> 5;
    if ((threadIdx.x & 31) == 0) s_warp[w] = v;
    __syncthreads();
    double r = 0;
    if (threadIdx.x == 0) for (int i = 0; i < (SEL_T / 32); i++) r += s_warp[i];
    __syncthreads();
    return r;
}

#define MBIT(i) ((s_mask[(i) >> 5] >> ((i) & 31)) & 1u)

// ---------------- per-row selection + loss (candidate-driven) ------------------
__global__ void __launch_bounds__(SEL_T, 4) select_kernel(const int* __restrict__ label,
                                                          const float* __restrict__ rand_neg) {
    __shared__ unsigned s_mask[NW_MASK];
    __shared__ unsigned s_ck[SCAP];
    __shared__ unsigned s_rk[SCAP];
    __shared__ int      s_ri[SCAP];
    __shared__ int      hist[2048];
    __shared__ unsigned s_posk[MEM_SIZE];
    __shared__ int      s_coarse[256];
    __shared__ float    s_posv[POS_NUM];
    __shared__ int      s_tie[256];
    __shared__ double   s_warp[SEL_T / 32];
    __shared__ int      s_b, s_kk, s_cnt;
    __shared__ double   s_Sh, s_Sr;

    int n = blockIdx.x;
    int tid = threadIdx.x;
    int lab = label[n];
    const float* ap  = g_ap + (size_t)n * BANK_ROWS;
    const float* rnd = rand_neg + (size_t)n * BANK_ROWS;

    for (int w = tid; w < NW_MASK; w += SEL_T) s_mask[w] = g_masks[lab][w];
    __syncthreads();

    // ===== hard negatives =====
    int rawH = g_cntH[n];
    if (tid == 0) s_cnt = 0;
    __syncthreads();
    {
        int lim = rawH < CAPG ? rawH : CAPG;
        for (int j = tid; j < lim; j += SEL_T) {
            int idx = g_candHi[n][j];
            if (MBIT(idx)) {
                int p = atomicAdd(&s_cnt, 1);
                if (p < SCAP) s_ck[p] = g_candHk[n][j];
            }
        }
    }
    __syncthreads();
    int vH = s_cnt;
    if (rawH <= CAPG && vH >= NEG_NUM && vH <= SCAP) {
        int needH;
        unsigned Th = cand_radix(s_ck, vH, NEG_NUM, 32, 0u, hist, s_coarse, &s_b, &s_kk, &needH);
        double sumH = 0.0;
        for (int j = tid; j < vH; j += SEL_T) {
            unsigned k = s_ck[j];
            if (k < Th) sumH += (double)__expf(key_dec(~k));
        }
        double Sh = block_red(sumH, s_warp);
        if (tid == 0) s_Sh = Sh + (double)needH * (double)__expf(key_dec(~Th));
    } else {
        int needH;
        unsigned Th = glob_radix(0, ap, rnd, s_mask, NEG_NUM, hist, s_coarse, &s_b, &s_kk, &needH);
        double sumH = 0.0;
        for (int i = tid; i < BANK_ROWS; i += SEL_T) {
            if (MBIT(i)) {
                float v = ap[i];
                if (~key_asc(v) < Th) sumH += (double)__expf(v);
            }
        }
        double Sh = block_red(sumH, s_warp);
        if (tid == 0) s_Sh = Sh + (double)needH * (double)__expf(key_dec(~Th));
    }
    __syncthreads();

    // ===== random negatives =====
    int rawR = g_cntR[n];
    if (tid == 0) s_cnt = 0;
    __syncthreads();
    {
        int lim = rawR < CAPG ? rawR : CAPG;
        for (int j = tid; j < lim; j += SEL_T) {
            int idx = g_candRi[n][j];
            if (MBIT(idx)) {
                int p = atomicAdd(&s_cnt, 1);
                if (p < SCAP) { s_rk[p] = g_candRk[n][j]; s_ri[p] = idx; }
            }
        }
    }
    __syncthreads();
    int vR = s_cnt;
    if (rawR <= CAPG && vR >= NEG_NUM && vR <= SCAP) {
        int needR;
        unsigned Tr = cand_radix(s_rk, vR, NEG_NUM, 32, 0u, hist, s_coarse, &s_b, &s_kk, &needR);
        if (tid == 0) s_cnt = 0;
        __syncthreads();
        double sumR = 0.0;
        for (int j = tid; j < vR; j += SEL_T) {
            unsigned k = s_rk[j];
            if (k < Tr) sumR += (double)__expf(ap[s_ri[j]]);
            else if (k == Tr) {
                int p = atomicAdd(&s_cnt, 1);
                if (p < 256) s_tie[p] = s_ri[j];
            }
        }
        __syncthreads();
        double Sr = block_red(sumR, s_warp);
        if (tid == 0) {
            int c = s_cnt < 256 ? s_cnt : 256;
            int take = needR < c ? needR : c;
            double add = 0.0;
            for (int t = 0; t < take; t++) {          // smallest column indices first
                int best = 0x7fffffff, bi = -1;
                for (int j = 0; j < c; j++)
                    if (s_tie[j] >= 0 && s_tie[j] < best) { best = s_tie[j]; bi = j; }
                s_tie[bi] = -1;
                add += (double)__expf(ap[best]);
            }
            s_Sr = Sr + add;
        }
    } else {
        int needR;
        unsigned Tr = glob_radix(1, ap, rnd, s_mask, NEG_NUM, hist, s_coarse, &s_b, &s_kk, &needR);
        if (tid == 0) s_cnt = 0;
        __syncthreads();
        double sumR = 0.0;
        for (int i = tid; i < BANK_ROWS; i += SEL_T) {
            if (MBIT(i)) {
                unsigned kr = key_asc(rnd[i]);
                if (kr < Tr) sumR += (double)__expf(ap[i]);
                else if (kr == Tr) {
                    int p = atomicAdd(&s_cnt, 1);
                    if (p < 256) s_tie[p] = i;
                }
            }
        }
        __syncthreads();
        double Sr = block_red(sumR, s_warp);
        if (tid == 0) {
            int c = s_cnt < 256 ? s_cnt : 256;
            int take = needR < c ? needR : c;
            double add = 0.0;
            for (int t = 0; t < take; t++) {
                int best = 0x7fffffff, bi = -1;
                for (int j = 0; j < c; j++)
                    if (s_tie[j] >= 0 && s_tie[j] < best) { best = s_tie[j]; bi = j; }
                s_tie[bi] = -1;
                add += (double)__expf(ap[best]);
            }
            s_Sr = Sr + add;
        }
    }
    __syncthreads();

    // ===== positives: 684 gathers + smem radix =====
    for (int i = tid; i < MEM_SIZE; i += SEL_T) {
        int m = lab + CLASS_NUM * i;
        s_posk[i] = (g_flag[m] > 0.f) ? key_asc(ap[m]) : 0xFFFFFFFFu;
    }
    __syncthreads();
    int needP;
    unsigned Tp = cand_radix(s_posk, MEM_SIZE, POS_NUM, 32, 0u, hist, s_coarse, &s_b, &s_kk, &needP);
    if (tid == 0) s_cnt = 0;
    __syncthreads();
    for (int i = tid; i < MEM_SIZE; i += SEL_T) {
        unsigned k = s_posk[i];
        if (k < Tp) {
            int p = atomicAdd(&s_cnt, 1);
            s_posv[p] = key_dec(k);
        }
    }
    __syncthreads();
    if (tid == 0) {
        float tv = key_dec(Tp);
        int base = s_cnt;                              // == POS_NUM - needP
        for (int t = 0; t < needP; t++) s_posv[base + t] = tv;
    }
    __syncthreads();

    // ===== loss partial =====
    double Shv = s_Sh, Srv = s_Sr;
    double l = 0.0;
    if (tid < POS_NUM) {
        double p = (double)s_posv[tid];
        double ep = exp(p);
        l = 2.0 * p - log(ep + Shv) - log(ep + Srv);
    }
    double tot = block_red(l, s_warp);
    if (tid == 0) g_partial[n] = tot;
}

// ---------------- finalize ------------------------------------------------------
__global__ void finalize_kernel(float* __restrict__ out) {
    __shared__ double s_warp[16];
    int tid = threadIdx.x;
    double v = g_partial[tid];
#pragma unroll
    for (int o = 16; o; o >>= 1) v += __shfl_down_sync(0xffffffffu, v, o);
    if ((tid & 31) == 0) s_warp[tid >> 5] = v;
    __syncthreads();
    if (tid == 0) {
        double t = 0;
        for (int i = 0; i < 16; i++) t += s_warp[i];
        out[0] = (float)(-t / (double)(BATCH * 2 * POS_NUM));
    }
}

// ---------------- launch --------------------------------------------------------
extern "C" void kernel_launch(void* const* d_in, const int* in_sizes, int n_in,
                              void* d_out, int out_size) {
    const float* f        = (const float*)d_in[0];
    const int*   label    = (const int*)d_in[1];
    const int*   enq      = (const int*)d_in[2];
    const float* bank     = (const float*)d_in[3];
    const float* flag     = (const float*)d_in[4];
    const float* rand_neg = (const float*)d_in[5];
    float* out = (float*)d_out;

    convert_kernel<<<1024, 256>>>(bank, flag, f);   // also zeroes candidate counters
    scatter_kernel<<<BATCH, 64>>>(f, enq);
    mask_kernel<<<CLASS_NUM, 256>>>();
    dim3 g(BANK_PAD / 128, BATCH / 128);
    gemm_mma_kernel<<<g, 256>>>();
    filter_kernel<<<dim3(4, BATCH), 256>>>(rand_neg);
    select_kernel<<<BATCH, SEL_T>>>(label, rand_neg);
    finalize_kernel<<<1, 512>>>(out);
}